// round 16
// baseline (speedup 1.0000x reference)
#include <cuda_runtime.h>
#include <cuda_bf16.h>
#include <cstdint>

#define NN 50000
#define DD 256
#define HH 8
#define HDIM 32
#define EE 800000
#define ET (EE + NN)   // edges + self loops
#define SCAN_B 512
#define NBLK ((NN + SCAN_B - 1) / SCAN_B)   // 98

// ---------------- scratch (device globals: allocation-free) ----------------
__device__ float    g_xp[NN * DD];     // x @ W (fp32, attention path)
__device__ uint32_t g_xt[NN * DD];     // tf32 bits of x (GEMM0 A operand)
__device__ float    g_as[NN * HH];
__device__ float    g_ad[NN * HH];
__device__ float    g_out[NN * DD];    // normalized aggregated messages
__device__ uint32_t g_hn[NN * DD];     // layernorm output (tf32 bits)
__device__ uint32_t g_mid[NN * DD];    // FFN hidden (tf32 bits)
__device__ uint32_t g_wt[3 * DD * DD]; // tf32 bits of W^T, W1^T, W2^T (n-major [n][k])
__device__ int      g_dummy;
// CSR scratch
__device__ int      g_cnt[NN];
__device__ int      g_cur[NN];
__device__ int      g_rs[NN + 1];
__device__ int      g_bsum[NBLK];
__device__ int      g_boff[NBLK];
__device__ int      g_col[ET];         // src per dst-grouped edge

// ---------------- dummy (aligns ncu capture slot = launch idx 3 on gemm0) ---
__global__ void dummy_k() { if (threadIdx.x == 0) g_dummy = 1; }

// ---------------- tf32 helpers ----------------------------------------------
__device__ __forceinline__ uint32_t f2tf32(float f) {
    uint32_t u;
    asm("cvt.rna.tf32.f32 %0, %1;" : "=r"(u) : "f"(f));
    return u;
}
__device__ __forceinline__ void mma_tf32(
    float& d0, float& d1, float& d2, float& d3,
    uint32_t a0, uint32_t a1, uint32_t a2, uint32_t a3,
    uint32_t b0, uint32_t b1)
{
    asm volatile(
        "mma.sync.aligned.m16n8k8.row.col.f32.tf32.tf32.f32 "
        "{%0,%1,%2,%3}, {%4,%5,%6,%7}, {%8,%9}, {%0,%1,%2,%3};"
        : "+f"(d0), "+f"(d1), "+f"(d2), "+f"(d3)
        : "r"(a0), "r"(a1), "r"(a2), "r"(a3), "r"(b0), "r"(b1));
}
__device__ __forceinline__ void ldsm_x4(
    uint32_t& d0, uint32_t& d1, uint32_t& d2, uint32_t& d3, uint32_t addr)
{
    asm volatile("ldmatrix.sync.aligned.m8n8.x4.shared.b16 {%0,%1,%2,%3}, [%4];"
                 : "=r"(d0), "=r"(d1), "=r"(d2), "=r"(d3) : "r"(addr));
}
__device__ __forceinline__ uint32_t smem_u32(const void* p) {
    uint32_t a;
    asm("{ .reg .u64 t; cvta.to.shared.u64 t, %1; cvt.u32.u64 %0, t; }"
        : "=r"(a) : "l"(p));
    return a;
}
__device__ __forceinline__ void cp_async16(uint32_t dst, const void* src, bool pred) {
    int sz = pred ? 16 : 0;
    asm volatile("cp.async.cg.shared.global [%0], [%1], 16, %2;"
                 :: "r"(dst), "l"(src), "r"(sz) : "memory");
}
#define CP_COMMIT() asm volatile("cp.async.commit_group;" ::: "memory")

// ---------------- tf32 mma.sync GEMM (cp.async + ldmatrix fragments) --------
// A row-major [m][k]; B = pre-transposed weights, n-major [n][k].
// Both smem tiles stride 36 u32 (== 4 mod 32): ldmatrix row starts hit banks
// 4i -> each 8-row fetch covers all 32 banks exactly once (conflict-free).
// Per ks-step: 2 A-ldmatrix.x4 + 4 B-ldmatrix.x4 (vs 24 scalar LDS before).
#define TS_STRIDE 36
#define A_U32    (128 * TS_STRIDE)          // 4608
#define STAGE_U32 (2 * A_U32)               // 9216 (A tile + B tile)
#define SMEM_BYTES (2 * STAGE_U32 * 4)      // 73728 B

template <int EPI, bool TF32OUT, bool DOATT>
__global__ __launch_bounds__(256) void tf32_gemm_k(
    const uint32_t* __restrict__ A, const uint32_t* __restrict__ B,
    const float* __restrict__ bias, float* __restrict__ C,
    const float* __restrict__ att_s, const float* __restrict__ att_d, int M)
{
    extern __shared__ uint32_t sm[];
    const uint32_t smb = smem_u32(sm);

    const int tid = threadIdx.x;
    const int wid = tid >> 5, lane = tid & 31;
    const int g = lane >> 2, r = lane & 3;
    const int wm = (wid & 3) * 32;
    const int wn = (wid >> 2) * 64;
    const int row0 = blockIdx.x * 128;
    const int nb = blockIdx.y * 128;

    // staging coords: A and B each 1024 float4, 4 per thread
    int a_row[4], a_kv[4], b_nl[4], b_kv[4];
    bool a_ok[4];
#pragma unroll
    for (int it = 0; it < 4; it++) {
        int idx = tid + it * 256;
        a_row[it] = idx >> 3;
        a_kv[it]  = (idx & 7) * 4;
        a_ok[it]  = (row0 + a_row[it]) < M;
        b_nl[it]  = idx >> 3;           // local n row 0..127
        b_kv[it]  = (idx & 7) * 4;      // k offset within chunk
    }

    // ldmatrix lane offsets (u32 units within a stage tile)
    const int seg = lane >> 3, i8 = lane & 7;
    const int rowadd = (seg >> 1) * 8 + i8;
    const int kadd = (seg & 1) * 4;
    int off_a[2], off_b[4];
#pragma unroll
    for (int mi = 0; mi < 2; mi++)
        off_a[mi] = (wm + mi * 16 + rowadd) * TS_STRIDE + kadd;
#pragma unroll
    for (int p = 0; p < 4; p++)
        off_b[p] = (wn + 16 * p + rowadd) * TS_STRIDE + kadd;

    float acc[2][8][4];
#pragma unroll
    for (int mi = 0; mi < 2; mi++)
#pragma unroll
        for (int ni = 0; ni < 8; ni++)
#pragma unroll
            for (int q = 0; q < 4; q++) acc[mi][ni][q] = 0.f;

    auto stage = [&](int kc, int s) {
        const int k0 = kc * 32;
        const uint32_t asb = smb + s * (STAGE_U32 * 4);
        const uint32_t bsb = asb + A_U32 * 4;
#pragma unroll
        for (int it = 0; it < 4; it++) {
            int arow = a_ok[it] ? (row0 + a_row[it]) : 0;
            cp_async16(asb + (a_row[it] * TS_STRIDE + a_kv[it]) * 4,
                       A + (size_t)arow * DD + k0 + a_kv[it], a_ok[it]);
            cp_async16(bsb + (b_nl[it] * TS_STRIDE + b_kv[it]) * 4,
                       B + (size_t)(nb + b_nl[it]) * DD + k0 + b_kv[it], true);
        }
        CP_COMMIT();
    };

    stage(0, 0);

    for (int kc = 0; kc < 8; kc++) {
        if (kc < 7) {
            stage(kc + 1, (kc + 1) & 1);
            asm volatile("cp.async.wait_group 1;" ::: "memory");
        } else {
            asm volatile("cp.async.wait_group 0;" ::: "memory");
        }
        __syncthreads();

        const uint32_t As_b = smb + (kc & 1) * (STAGE_U32 * 4);
        const uint32_t Bs_b = As_b + A_U32 * 4;

#pragma unroll
        for (int ks = 0; ks < 4; ks++) {
            const int kk = ks * 8;
            uint32_t af[2][4];
#pragma unroll
            for (int mi = 0; mi < 2; mi++)
                ldsm_x4(af[mi][0], af[mi][2], af[mi][1], af[mi][3],
                        As_b + (off_a[mi] + kk) * 4);
            uint32_t bf[8][2];
#pragma unroll
            for (int p = 0; p < 4; p++)
                ldsm_x4(bf[2 * p][0], bf[2 * p][1],
                        bf[2 * p + 1][0], bf[2 * p + 1][1],
                        Bs_b + (off_b[p] + kk) * 4);
#pragma unroll
            for (int mi = 0; mi < 2; mi++)
#pragma unroll
                for (int ni = 0; ni < 8; ni++)
                    mma_tf32(acc[mi][ni][0], acc[mi][ni][1],
                             acc[mi][ni][2], acc[mi][ni][3],
                             af[mi][0], af[mi][1], af[mi][2], af[mi][3],
                             bf[ni][0], bf[ni][1]);
        }
        __syncthreads();
    }

#pragma unroll
    for (int mi = 0; mi < 2; mi++) {
#pragma unroll
        for (int half = 0; half < 2; half++) {
            int grow = row0 + wm + mi * 16 + g + half * 8;
            if (grow >= M) continue;
            float asp[2] = {0.f, 0.f}, adp[2] = {0.f, 0.f};
#pragma unroll
            for (int ni = 0; ni < 8; ni++) {
                int col = nb + wn + ni * 8 + 2 * r;
                float2 v = make_float2(acc[mi][ni][half * 2],
                                       acc[mi][ni][half * 2 + 1]);
                if (DOATT) {
                    int hh = ni >> 2;
                    asp[hh] += v.x * __ldg(&att_s[col]) + v.y * __ldg(&att_s[col + 1]);
                    adp[hh] += v.x * __ldg(&att_d[col]) + v.y * __ldg(&att_d[col + 1]);
                }
                if (EPI >= 1) {
                    v.x += bias[col];
                    v.y += bias[col + 1];
                }
                if (EPI == 1) {
                    v.x = fmaxf(v.x, 0.f);
                    v.y = fmaxf(v.y, 0.f);
                }
                if (TF32OUT) {
                    v.x = __uint_as_float(f2tf32(v.x));
                    v.y = __uint_as_float(f2tf32(v.y));
                }
                *(float2*)(C + (size_t)grow * DD + col) = v;
            }
            if (DOATT) {
#pragma unroll
                for (int hh = 0; hh < 2; hh++) {
                    float a = asp[hh], b = adp[hh];
                    a += __shfl_xor_sync(0xffffffffu, a, 1);
                    a += __shfl_xor_sync(0xffffffffu, a, 2);
                    b += __shfl_xor_sync(0xffffffffu, b, 1);
                    b += __shfl_xor_sync(0xffffffffu, b, 2);
                    if (r == 0) {
                        int h = ((nb + wn) >> 5) + hh;
                        g_as[grow * HH + h] = a;
                        g_ad[grow * HH + h] = b;
                    }
                }
            }
        }
    }
}

// ---------------- prep: zero CSR counters + convert x to tf32 ---------------
__global__ void prep_k(const float4* __restrict__ x) {
    int idx = blockIdx.x * blockDim.x + threadIdx.x;
    if (idx < NN * DD / 4) {
        float4 v = x[idx];
        ((uint4*)g_xt)[idx] = make_uint4(f2tf32(v.x), f2tf32(v.y),
                                         f2tf32(v.z), f2tf32(v.w));
    }
    if (idx < NN) {
        g_cnt[idx] = 0;
        g_cur[idx] = 0;
    }
}

// ---------------- weight transpose + tf32 conversion -------------------------
// g_wt[z][n*256+k] = tf32(src_z[k*256+n])
__global__ void wconv_k(const float* __restrict__ W,
                        const float* __restrict__ W1,
                        const float* __restrict__ W2)
{
    __shared__ float t[32][33];
    const float* src = (blockIdx.z == 0) ? W : (blockIdx.z == 1) ? W1 : W2;
    uint32_t* dst = g_wt + blockIdx.z * DD * DD;
    int bx = blockIdx.x * 32, by = blockIdx.y * 32;
    int tx = threadIdx.x, ty = threadIdx.y;
#pragma unroll
    for (int i = 0; i < 4; i++)
        t[ty + 8 * i][tx] = src[(by + ty + 8 * i) * DD + bx + tx];   // [k][n]
    __syncthreads();
#pragma unroll
    for (int i = 0; i < 4; i++)
        dst[(bx + ty + 8 * i) * DD + by + tx] = f2tf32(t[tx][ty + 8 * i]);
}

// ---------------- CSR build --------------------------------------------------
__global__ __launch_bounds__(256) void csr_count_k(const int* __restrict__ ei) {
    int e = blockIdx.x * blockDim.x + threadIdx.x;
    if (e >= ET) return;
    int src, dst;
    if (e < EE) { src = ei[e]; dst = ei[EE + e]; }
    else        { src = dst = e - EE; }
    if ((unsigned)src >= NN || (unsigned)dst >= NN) return;
    atomicAdd(&g_cnt[dst], 1);
}

__global__ __launch_bounds__(SCAN_B) void scan1_k() {
    __shared__ int s[SCAN_B];
    int i = blockIdx.x * SCAN_B + threadIdx.x;
    s[threadIdx.x] = (i < NN) ? g_cnt[i] : 0;
    __syncthreads();
#pragma unroll
    for (int off = SCAN_B / 2; off > 0; off >>= 1) {
        if (threadIdx.x < off) s[threadIdx.x] += s[threadIdx.x + off];
        __syncthreads();
    }
    if (threadIdx.x == 0) g_bsum[blockIdx.x] = s[0];
}

__global__ void scan2_k() {
    if (threadIdx.x == 0) {
        int t = 0;
        for (int b = 0; b < NBLK; b++) {
            g_boff[b] = t;
            t += g_bsum[b];
        }
        g_rs[NN] = t;
    }
}

__global__ __launch_bounds__(SCAN_B) void scan3_k() {
    __shared__ int s[SCAN_B];
    int i = blockIdx.x * SCAN_B + threadIdx.x;
    int v = (i < NN) ? g_cnt[i] : 0;
    s[threadIdx.x] = v;
    __syncthreads();
#pragma unroll
    for (int off = 1; off < SCAN_B; off <<= 1) {
        int t = (threadIdx.x >= off) ? s[threadIdx.x - off] : 0;
        __syncthreads();
        s[threadIdx.x] += t;
        __syncthreads();
    }
    if (i < NN) g_rs[i] = g_boff[blockIdx.x] + s[threadIdx.x] - v;  // exclusive
}

__global__ __launch_bounds__(256) void csr_fill_k(const int* __restrict__ ei) {
    int e = blockIdx.x * blockDim.x + threadIdx.x;
    if (e >= ET) return;
    int src, dst;
    if (e < EE) { src = ei[e]; dst = ei[EE + e]; }
    else        { src = dst = e - EE; }
    if ((unsigned)src >= NN || (unsigned)dst >= NN) return;
    int pos = atomicAdd(&g_cur[dst], 1);
    g_col[g_rs[dst] + pos] = src;
}

// ---------------- gather aggregation (no atomics) ----------------------------
__global__ __launch_bounds__(256) void agg_k() {
    const int tid = threadIdx.x;
    const int n = blockIdx.x * 4 + (tid >> 6);
    if (n >= NN) return;
    const int g = tid & 63, h = g >> 3, c = (g & 7) << 2;
    const float ad_h = g_ad[n * HH + h];
    const int start = g_rs[n], end = g_rs[n + 1];
    float4 acc = make_float4(0.f, 0.f, 0.f, 0.f);
    float den = 0.f;
    for (int j = start; j < end; j++) {
        int src = g_col[j];
        float v = g_as[src * HH + h] + ad_h;
        v = (v > 0.f) ? v : 0.2f * v;           // leaky relu
        float w = __expf(v);
        den += w;
        const float4 xv = *(const float4*)&g_xp[src * DD + h * HDIM + c];
        acc.x += w * xv.x;
        acc.y += w * xv.y;
        acc.z += w * xv.z;
        acc.w += w * xv.w;
    }
    float inv = 1.f / (den + 1e-16f);
    *(float4*)&g_out[n * DD + g * 4] =
        make_float4(acc.x * inv, acc.y * inv, acc.z * inv, acc.w * inv);
}

// ---------------- bias + residual + LayerNorm (tf32 out) --------------------
__global__ __launch_bounds__(256) void lnorm_k(
    const float* __restrict__ x, const float* __restrict__ bias,
    const float* __restrict__ lg, const float* __restrict__ lb)
{
    const int tid = threadIdx.x, warp = tid >> 5, lane = tid & 31;
    const int n = blockIdx.x * 8 + warp;
    if (n >= NN) return;
    float r[8];
    float s = 0.f;
#pragma unroll
    for (int i = 0; i < 8; i++) {
        int c = i * 32 + lane;
        r[i] = g_out[n * DD + c] + bias[c] + x[n * DD + c];
        s += r[i];
    }
#pragma unroll
    for (int o = 16; o; o >>= 1) s += __shfl_xor_sync(0xffffffffu, s, o);
    float mu = s * (1.f / 256.f);
    float q = 0.f;
#pragma unroll
    for (int i = 0; i < 8; i++) {
        float d = r[i] - mu;
        q += d * d;
    }
#pragma unroll
    for (int o = 16; o; o >>= 1) q += __shfl_xor_sync(0xffffffffu, q, o);
    float inv = rsqrtf(q * (1.f / 256.f) + 1e-5f);
#pragma unroll
    for (int i = 0; i < 8; i++) {
        int c = i * 32 + lane;
        g_hn[n * DD + c] = f2tf32((r[i] - mu) * inv * lg[c] + lb[c]);
    }
}

// ---------------- launch ----------------------------------------------------
extern "C" void kernel_launch(void* const* d_in, const int* in_sizes, int n_in,
                              void* d_out, int out_size) {
    const float* x        = (const float*)d_in[0];
    const int* ei         = (const int*)d_in[1];   // int32 edge_index [2,E]
    // d_in[2] = edge_attr (unused)
    const float* W        = (const float*)d_in[3];
    const float* att_src  = (const float*)d_in[4];
    const float* att_dst  = (const float*)d_in[5];
    const float* bias     = (const float*)d_in[6];
    const float* ln_g     = (const float*)d_in[7];
    const float* ln_b     = (const float*)d_in[8];
    const float* W1       = (const float*)d_in[9];
    const float* b1       = (const float*)d_in[10];
    const float* W2       = (const float*)d_in[11];
    const float* b2       = (const float*)d_in[12];
    float* out            = (float*)d_out;

    float*    xp  = nullptr; cudaGetSymbolAddress((void**)&xp,  g_xp);
    uint32_t* xt  = nullptr; cudaGetSymbolAddress((void**)&xt,  g_xt);
    uint32_t* hn  = nullptr; cudaGetSymbolAddress((void**)&hn,  g_hn);
    uint32_t* mid = nullptr; cudaGetSymbolAddress((void**)&mid, g_mid);
    uint32_t* wt  = nullptr; cudaGetSymbolAddress((void**)&wt,  g_wt);

    cudaFuncSetAttribute(tf32_gemm_k<0, false, true>,
                         cudaFuncAttributeMaxDynamicSharedMemorySize, SMEM_BYTES);
    cudaFuncSetAttribute(tf32_gemm_k<1, true, false>,
                         cudaFuncAttributeMaxDynamicSharedMemorySize, SMEM_BYTES);
    cudaFuncSetAttribute(tf32_gemm_k<2, false, false>,
                         cudaFuncAttributeMaxDynamicSharedMemorySize, SMEM_BYTES);

    const dim3 GEMM_GRID((NN + 127) / 128, 2);

    // 0. dummy (capture slot = launch idx 3 -> gemm0)
    dummy_k<<<1, 32>>>();

    // 1. weights -> transposed tf32 [n][k]
    wconv_k<<<dim3(8, 8, 3), dim3(32, 8)>>>(W, W1, W2);

    // 2. zero CSR counters + x -> tf32
    prep_k<<<(NN * DD / 4 + 255) / 256, 256>>>((const float4*)x);

    // 3. xp = x @ W  (+fused attention dot-products)
    tf32_gemm_k<0, false, true><<<GEMM_GRID, 256, SMEM_BYTES>>>(
        xt, wt, nullptr, xp, att_src, att_dst, NN);

    // 4. CSR build: histogram -> scan -> fill
    csr_count_k<<<(ET + 255) / 256, 256>>>(ei);
    scan1_k<<<NBLK, SCAN_B>>>();
    scan2_k<<<1, 32>>>();
    scan3_k<<<NBLK, SCAN_B>>>();
    csr_fill_k<<<(ET + 255) / 256, 256>>>(ei);

    // 5. gather aggregation (atomic-free, register softmax denominator)
    agg_k<<<(NN + 3) / 4, 256>>>();

    // 6. bias + residual + layernorm (tf32 bits out)
    lnorm_k<<<(NN + 7) / 8, 256>>>(x, bias, ln_g, ln_b);

    // 7. FFN
    tf32_gemm_k<1, true, false><<<GEMM_GRID, 256, SMEM_BYTES>>>(
        hn, wt + DD * DD, b1, (float*)mid, nullptr, nullptr, NN);
    tf32_gemm_k<2, false, false><<<GEMM_GRID, 256, SMEM_BYTES>>>(
        mid, wt + 2 * DD * DD, b2, out, nullptr, nullptr, NN);
}

// round 17
// speedup vs baseline: 1.1082x; 1.1082x over previous
#include <cuda_runtime.h>
#include <cuda_bf16.h>
#include <cstdint>

#define NN 50000
#define DD 256
#define HH 8
#define HDIM 32
#define EE 800000
#define ET (EE + NN)   // edges + self loops
#define SCAN_B 512
#define NBLK ((NN + SCAN_B - 1) / SCAN_B)   // 98

// ---------------- scratch (device globals: allocation-free) ----------------
__device__ float    g_xp[NN * DD];     // x @ W (fp32, attention path)
__device__ uint32_t g_xt[NN * DD];     // tf32 bits of x (GEMM0 A operand)
__device__ float    g_as[NN * HH];
__device__ float    g_ad[NN * HH];
__device__ uint32_t g_hn[NN * DD];     // layernorm output (tf32 bits)
__device__ uint32_t g_mid[NN * DD];    // FFN hidden (tf32 bits)
__device__ uint32_t g_wt[3 * DD * DD]; // tf32 bits of W, W1, W2 ([k][n] row-major)
__device__ int      g_dummy;
// CSR scratch
__device__ int      g_cnt[NN];
__device__ int      g_cur[NN];
__device__ int      g_rs[NN + 1];
__device__ int      g_bsum[NBLK];
__device__ int      g_boff[NBLK];
__device__ int      g_col[ET];         // src per dst-grouped edge

// ---------------- dummy (aligns ncu capture slot = launch idx 3 on gemm0) ---
__global__ void dummy_k() { if (threadIdx.x == 0) g_dummy = 1; }

// ---------------- tf32 helpers ----------------------------------------------
__device__ __forceinline__ uint32_t f2tf32(float f) {
    uint32_t u;
    asm("cvt.rna.tf32.f32 %0, %1;" : "=r"(u) : "f"(f));
    return u;
}
__device__ __forceinline__ void mma_tf32(
    float& d0, float& d1, float& d2, float& d3,
    uint32_t a0, uint32_t a1, uint32_t a2, uint32_t a3,
    uint32_t b0, uint32_t b1)
{
    asm volatile(
        "mma.sync.aligned.m16n8k8.row.col.f32.tf32.tf32.f32 "
        "{%0,%1,%2,%3}, {%4,%5,%6,%7}, {%8,%9}, {%0,%1,%2,%3};"
        : "+f"(d0), "+f"(d1), "+f"(d2), "+f"(d3)
        : "r"(a0), "r"(a1), "r"(a2), "r"(a3), "r"(b0), "r"(b1));
}
__device__ __forceinline__ uint32_t smem_u32(const void* p) {
    uint32_t a;
    asm("{ .reg .u64 t; cvta.to.shared.u64 t, %1; cvt.u32.u64 %0, t; }"
        : "=r"(a) : "l"(p));
    return a;
}
__device__ __forceinline__ void cp_async16(uint32_t dst, const void* src, bool pred) {
    int sz = pred ? 16 : 0;
    asm volatile("cp.async.cg.shared.global [%0], [%1], 16, %2;"
                 :: "r"(dst), "l"(src), "r"(sz) : "memory");
}
#define CP_COMMIT() asm volatile("cp.async.commit_group;" ::: "memory")

// ---------------- tf32 mma.sync GEMM (R14-proven: cp.async + scalar LDS) ----
// B is [K,N] row-major. BS_STRIDE 136 (== 8 mod 32): conflict-free fragments.
#define AS_STRIDE 36
#define BS_STRIDE 136
#define A_U32    (128 * AS_STRIDE)          // 4608
#define STAGE_U32 (A_U32 + 32 * BS_STRIDE)  // 8960
#define SMEM_BYTES (2 * STAGE_U32 * 4)      // 71680 B

template <int EPI, bool TF32OUT, bool DOATT>
__global__ __launch_bounds__(256) void tf32_gemm_k(
    const uint32_t* __restrict__ A, const uint32_t* __restrict__ B,
    const float* __restrict__ bias, float* __restrict__ C,
    const float* __restrict__ att_s, const float* __restrict__ att_d, int M)
{
    extern __shared__ uint32_t sm[];
    const uint32_t smb = smem_u32(sm);

    const int tid = threadIdx.x;
    const int wid = tid >> 5, lane = tid & 31;
    const int g = lane >> 2, r = lane & 3;
    const int wm = (wid & 3) * 32;
    const int wn = (wid >> 2) * 64;
    const int row0 = blockIdx.x * 128;
    const int nb = blockIdx.y * 128;

    int a_row[4], a_kv[4], b_kr[4], b_nv[4];
    bool a_ok[4];
#pragma unroll
    for (int it = 0; it < 4; it++) {
        int idx = tid + it * 256;
        a_row[it] = idx >> 3;
        a_kv[it]  = (idx & 7) * 4;
        a_ok[it]  = (row0 + a_row[it]) < M;
        b_kr[it]  = idx >> 5;
        b_nv[it]  = (idx & 31) * 4;
    }

    float acc[2][8][4];
#pragma unroll
    for (int mi = 0; mi < 2; mi++)
#pragma unroll
        for (int ni = 0; ni < 8; ni++)
#pragma unroll
            for (int q = 0; q < 4; q++) acc[mi][ni][q] = 0.f;

    auto stage = [&](int kc, int s) {
        const int k0 = kc * 32;
        const uint32_t asb = smb + s * (STAGE_U32 * 4);
        const uint32_t bsb = asb + A_U32 * 4;
#pragma unroll
        for (int it = 0; it < 4; it++) {
            int arow = a_ok[it] ? (row0 + a_row[it]) : 0;
            cp_async16(asb + (a_row[it] * AS_STRIDE + a_kv[it]) * 4,
                       A + (size_t)arow * DD + k0 + a_kv[it], a_ok[it]);
            cp_async16(bsb + (b_kr[it] * BS_STRIDE + b_nv[it]) * 4,
                       B + (size_t)(k0 + b_kr[it]) * DD + nb + b_nv[it], true);
        }
        CP_COMMIT();
    };

    stage(0, 0);

    for (int kc = 0; kc < 8; kc++) {
        if (kc < 7) {
            stage(kc + 1, (kc + 1) & 1);
            asm volatile("cp.async.wait_group 1;" ::: "memory");
        } else {
            asm volatile("cp.async.wait_group 0;" ::: "memory");
        }
        __syncthreads();

        const uint32_t* As = sm + (kc & 1) * STAGE_U32;
        const uint32_t* Bs = As + A_U32;

#pragma unroll
        for (int ks = 0; ks < 4; ks++) {
            const int kk = ks * 8;
            uint32_t af[2][4];
#pragma unroll
            for (int mi = 0; mi < 2; mi++) {
                int mr = wm + mi * 16 + g;
                af[mi][0] = As[mr * AS_STRIDE + kk + r];
                af[mi][1] = As[(mr + 8) * AS_STRIDE + kk + r];
                af[mi][2] = As[mr * AS_STRIDE + kk + r + 4];
                af[mi][3] = As[(mr + 8) * AS_STRIDE + kk + r + 4];
            }
            uint32_t bf[8][2];
#pragma unroll
            for (int ni = 0; ni < 8; ni++) {
                int nc = wn + ni * 8 + g;
                bf[ni][0] = Bs[(kk + r) * BS_STRIDE + nc];
                bf[ni][1] = Bs[(kk + r + 4) * BS_STRIDE + nc];
            }
#pragma unroll
            for (int mi = 0; mi < 2; mi++)
#pragma unroll
                for (int ni = 0; ni < 8; ni++)
                    mma_tf32(acc[mi][ni][0], acc[mi][ni][1],
                             acc[mi][ni][2], acc[mi][ni][3],
                             af[mi][0], af[mi][1], af[mi][2], af[mi][3],
                             bf[ni][0], bf[ni][1]);
        }
        __syncthreads();
    }

#pragma unroll
    for (int mi = 0; mi < 2; mi++) {
#pragma unroll
        for (int half = 0; half < 2; half++) {
            int grow = row0 + wm + mi * 16 + g + half * 8;
            if (grow >= M) continue;
            float asp[2] = {0.f, 0.f}, adp[2] = {0.f, 0.f};
#pragma unroll
            for (int ni = 0; ni < 8; ni++) {
                int col = nb + wn + ni * 8 + 2 * r;
                float2 v = make_float2(acc[mi][ni][half * 2],
                                       acc[mi][ni][half * 2 + 1]);
                if (DOATT) {
                    int hh = ni >> 2;
                    asp[hh] += v.x * __ldg(&att_s[col]) + v.y * __ldg(&att_s[col + 1]);
                    adp[hh] += v.x * __ldg(&att_d[col]) + v.y * __ldg(&att_d[col + 1]);
                }
                if (EPI >= 1) {
                    v.x += bias[col];
                    v.y += bias[col + 1];
                }
                if (EPI == 1) {
                    v.x = fmaxf(v.x, 0.f);
                    v.y = fmaxf(v.y, 0.f);
                }
                if (TF32OUT) {
                    v.x = __uint_as_float(f2tf32(v.x));
                    v.y = __uint_as_float(f2tf32(v.y));
                }
                *(float2*)(C + (size_t)grow * DD + col) = v;
            }
            if (DOATT) {
#pragma unroll
                for (int hh = 0; hh < 2; hh++) {
                    float a = asp[hh], b = adp[hh];
                    a += __shfl_xor_sync(0xffffffffu, a, 1);
                    a += __shfl_xor_sync(0xffffffffu, a, 2);
                    b += __shfl_xor_sync(0xffffffffu, b, 1);
                    b += __shfl_xor_sync(0xffffffffu, b, 2);
                    if (r == 0) {
                        int h = ((nb + wn) >> 5) + hh;
                        g_as[grow * HH + h] = a;
                        g_ad[grow * HH + h] = b;
                    }
                }
            }
        }
    }
}

// ---------------- prep: zero CSR counters + convert x to tf32 ---------------
__global__ void prep_k(const float4* __restrict__ x) {
    int idx = blockIdx.x * blockDim.x + threadIdx.x;
    if (idx < NN * DD / 4) {
        float4 v = x[idx];
        ((uint4*)g_xt)[idx] = make_uint4(f2tf32(v.x), f2tf32(v.y),
                                         f2tf32(v.z), f2tf32(v.w));
    }
    if (idx < NN) {
        g_cnt[idx] = 0;
        g_cur[idx] = 0;
    }
}

// ---------------- weight conversion to tf32 ([k][n], no transpose) ----------
__global__ void wconv_k(const float4* __restrict__ W,
                        const float4* __restrict__ W1,
                        const float4* __restrict__ W2)
{
    int idx = blockIdx.x * blockDim.x + threadIdx.x;
    const int per = DD * DD / 4;
    if (idx >= 3 * per) return;
    int z = idx / per, j = idx % per;
    const float4 v = (z == 0 ? W : z == 1 ? W1 : W2)[j];
    ((uint4*)g_wt)[idx] = make_uint4(f2tf32(v.x), f2tf32(v.y),
                                     f2tf32(v.z), f2tf32(v.w));
}

// ---------------- CSR build --------------------------------------------------
__global__ __launch_bounds__(256) void csr_count_k(const int* __restrict__ ei) {
    int e = blockIdx.x * blockDim.x + threadIdx.x;
    if (e >= ET) return;
    int src, dst;
    if (e < EE) { src = ei[e]; dst = ei[EE + e]; }
    else        { src = dst = e - EE; }
    if ((unsigned)src >= NN || (unsigned)dst >= NN) return;
    atomicAdd(&g_cnt[dst], 1);
}

__global__ __launch_bounds__(SCAN_B) void scan1_k() {
    __shared__ int s[SCAN_B];
    int i = blockIdx.x * SCAN_B + threadIdx.x;
    s[threadIdx.x] = (i < NN) ? g_cnt[i] : 0;
    __syncthreads();
#pragma unroll
    for (int off = SCAN_B / 2; off > 0; off >>= 1) {
        if (threadIdx.x < off) s[threadIdx.x] += s[threadIdx.x + off];
        __syncthreads();
    }
    if (threadIdx.x == 0) g_bsum[blockIdx.x] = s[0];
}

__global__ void scan2_k() {
    if (threadIdx.x == 0) {
        int t = 0;
        for (int b = 0; b < NBLK; b++) {
            g_boff[b] = t;
            t += g_bsum[b];
        }
        g_rs[NN] = t;
    }
}

__global__ __launch_bounds__(SCAN_B) void scan3_k() {
    __shared__ int s[SCAN_B];
    int i = blockIdx.x * SCAN_B + threadIdx.x;
    int v = (i < NN) ? g_cnt[i] : 0;
    s[threadIdx.x] = v;
    __syncthreads();
#pragma unroll
    for (int off = 1; off < SCAN_B; off <<= 1) {
        int t = (threadIdx.x >= off) ? s[threadIdx.x - off] : 0;
        __syncthreads();
        s[threadIdx.x] += t;
        __syncthreads();
    }
    if (i < NN) g_rs[i] = g_boff[blockIdx.x] + s[threadIdx.x] - v;  // exclusive
}

__global__ __launch_bounds__(256) void csr_fill_k(const int* __restrict__ ei) {
    int e = blockIdx.x * blockDim.x + threadIdx.x;
    if (e >= ET) return;
    int src, dst;
    if (e < EE) { src = ei[e]; dst = ei[EE + e]; }
    else        { src = dst = e - EE; }
    if ((unsigned)src >= NN || (unsigned)dst >= NN) return;
    int pos = atomicAdd(&g_cur[dst], 1);
    g_col[g_rs[dst] + pos] = src;
}

// ---------------- gather aggregation + fused LayerNorm -----------------------
// 4 nodes per 256-thread block; 64 threads per node hold the full 256-wide
// row (float4 each). After the gather, bias+residual and a 2-warp LN
// reduction produce g_hn tf32 bits directly (no g_out round-trip).
__global__ __launch_bounds__(256) void agg_ln_k(
    const float* __restrict__ x, const float* __restrict__ bias,
    const float* __restrict__ lg, const float* __restrict__ lb)
{
    __shared__ float s_sum[4][2], s_sq[4][2];
    const int tid = threadIdx.x;
    const int nl = tid >> 6;                 // node slot 0..3
    const int n = blockIdx.x * 4 + nl;       // NN % 4 == 0: always valid
    const int g = tid & 63, h = g >> 3, c = (g & 7) << 2;
    const int wsel = (g >> 5) & 1;           // warp-within-node
    const int lane = tid & 31;

    const float ad_h = g_ad[n * HH + h];
    const int start = g_rs[n], end = g_rs[n + 1];
    float4 acc = make_float4(0.f, 0.f, 0.f, 0.f);
    float den = 0.f;
    for (int j = start; j < end; j++) {
        int src = g_col[j];
        float v = g_as[src * HH + h] + ad_h;
        v = (v > 0.f) ? v : 0.2f * v;           // leaky relu
        float w = __expf(v);
        den += w;
        const float4 xv = *(const float4*)&g_xp[src * DD + h * HDIM + c];
        acc.x += w * xv.x;
        acc.y += w * xv.y;
        acc.z += w * xv.z;
        acc.w += w * xv.w;
    }
    float inv_d = 1.f / (den + 1e-16f);

    // r = msg + bias + x   (this thread's 4 columns: col0 = g*4)
    const int col = g * 4;
    const float4 bv = *(const float4*)&bias[col];
    const float4 xv = *(const float4*)&x[n * DD + col];
    float4 rv;
    rv.x = acc.x * inv_d + bv.x + xv.x;
    rv.y = acc.y * inv_d + bv.y + xv.y;
    rv.z = acc.z * inv_d + bv.z + xv.z;
    rv.w = acc.w * inv_d + bv.w + xv.w;

    // LN reduction over the node's 64 threads (2 warps)
    float s = rv.x + rv.y + rv.z + rv.w;
    float q = rv.x * rv.x + rv.y * rv.y + rv.z * rv.z + rv.w * rv.w;
#pragma unroll
    for (int o = 16; o; o >>= 1) {
        s += __shfl_xor_sync(0xffffffffu, s, o);
        q += __shfl_xor_sync(0xffffffffu, q, o);
    }
    if (lane == 0) {
        s_sum[nl][wsel] = s;
        s_sq[nl][wsel] = q;
    }
    __syncthreads();
    float S = s_sum[nl][0] + s_sum[nl][1];
    float Q = s_sq[nl][0] + s_sq[nl][1];
    float mu = S * (1.f / 256.f);
    float var = Q * (1.f / 256.f) - mu * mu;
    float inv = rsqrtf(var + 1e-5f);

    const float4 gv = *(const float4*)&lg[col];
    const float4 bb = *(const float4*)&lb[col];
    uint4 hv;
    hv.x = f2tf32((rv.x - mu) * inv * gv.x + bb.x);
    hv.y = f2tf32((rv.y - mu) * inv * gv.y + bb.y);
    hv.z = f2tf32((rv.z - mu) * inv * gv.z + bb.z);
    hv.w = f2tf32((rv.w - mu) * inv * gv.w + bb.w);
    *(uint4*)&g_hn[n * DD + col] = hv;
}

// ---------------- launch ----------------------------------------------------
extern "C" void kernel_launch(void* const* d_in, const int* in_sizes, int n_in,
                              void* d_out, int out_size) {
    const float* x        = (const float*)d_in[0];
    const int* ei         = (const int*)d_in[1];   // int32 edge_index [2,E]
    // d_in[2] = edge_attr (unused)
    const float* W        = (const float*)d_in[3];
    const float* att_src  = (const float*)d_in[4];
    const float* att_dst  = (const float*)d_in[5];
    const float* bias     = (const float*)d_in[6];
    const float* ln_g     = (const float*)d_in[7];
    const float* ln_b     = (const float*)d_in[8];
    const float* W1       = (const float*)d_in[9];
    const float* b1       = (const float*)d_in[10];
    const float* W2       = (const float*)d_in[11];
    const float* b2       = (const float*)d_in[12];
    float* out            = (float*)d_out;

    float*    xp  = nullptr; cudaGetSymbolAddress((void**)&xp,  g_xp);
    uint32_t* xt  = nullptr; cudaGetSymbolAddress((void**)&xt,  g_xt);
    uint32_t* hn  = nullptr; cudaGetSymbolAddress((void**)&hn,  g_hn);
    uint32_t* mid = nullptr; cudaGetSymbolAddress((void**)&mid, g_mid);
    uint32_t* wt  = nullptr; cudaGetSymbolAddress((void**)&wt,  g_wt);

    cudaFuncSetAttribute(tf32_gemm_k<0, false, true>,
                         cudaFuncAttributeMaxDynamicSharedMemorySize, SMEM_BYTES);
    cudaFuncSetAttribute(tf32_gemm_k<1, true, false>,
                         cudaFuncAttributeMaxDynamicSharedMemorySize, SMEM_BYTES);
    cudaFuncSetAttribute(tf32_gemm_k<2, false, false>,
                         cudaFuncAttributeMaxDynamicSharedMemorySize, SMEM_BYTES);

    const dim3 GEMM_GRID((NN + 127) / 128, 2);

    // 0. dummy (capture slot = launch idx 3 -> gemm0)
    dummy_k<<<1, 32>>>();

    // 1. weights -> tf32 ([k][n], original layout)
    wconv_k<<<(3 * DD * DD / 4 + 255) / 256, 256>>>(
        (const float4*)W, (const float4*)W1, (const float4*)W2);

    // 2. zero CSR counters + x -> tf32
    prep_k<<<(NN * DD / 4 + 255) / 256, 256>>>((const float4*)x);

    // 3. xp = x @ W  (+fused attention dot-products)
    tf32_gemm_k<0, false, true><<<GEMM_GRID, 256, SMEM_BYTES>>>(
        xt, wt, nullptr, xp, att_src, att_dst, NN);

    // 4. CSR build: histogram -> scan -> fill
    csr_count_k<<<(ET + 255) / 256, 256>>>(ei);
    scan1_k<<<NBLK, SCAN_B>>>();
    scan2_k<<<1, 32>>>();
    scan3_k<<<NBLK, SCAN_B>>>();
    csr_fill_k<<<(ET + 255) / 256, 256>>>(ei);

    // 5. gather aggregation + fused bias/residual/LayerNorm (tf32 bits out)
    agg_ln_k<<<NN / 4, 256>>>(x, bias, ln_g, ln_b);

    // 6. FFN
    tf32_gemm_k<1, true, false><<<GEMM_GRID, 256, SMEM_BYTES>>>(
        hn, wt + DD * DD, b1, (float*)mid, nullptr, nullptr, NN);
    tf32_gemm_k<2, false, false><<<GEMM_GRID, 256, SMEM_BYTES>>>(
        mid, wt + 2 * DD * DD, b2, out, nullptr, nullptr, NN);
}